// round 1
// baseline (speedup 1.0000x reference)
#include <cuda_runtime.h>
#include <cuda_bf16.h>
#include <mma.h>

using namespace nvcuda;

#define B_SZ 65536
#define D_SZ 256
#define F_SZ 512
#define P_SZ 256

// ---------------- scratch (static device globals; no allocations) ----------------
__device__ __nv_bfloat16 g_W1[P_SZ * F_SZ];          // theta*pw + alpha*pp
__device__ __nv_bfloat16 g_W2[P_SZ * F_SZ];          // beta*pw
__device__ float         g_biasP[P_SZ];              // -beta * pws[p]
__device__ __nv_bfloat16 g_R[(size_t)B_SZ * F_SZ];   // relu(x @ features^T), 64 MB
__device__ float         g_rowbias[B_SZ];            // -alpha * sum_f r^2

// =========================== kernel 1: p-side precompute ===========================
__global__ __launch_bounds__(256)
void pside_kernel(const float* __restrict__ prototypes,
                  const float* __restrict__ features,
                  const float* __restrict__ alpha,
                  const float* __restrict__ beta,
                  const float* __restrict__ theta) {
    int p = blockIdx.x;
    int t = threadIdx.x;
    __shared__ float proto_s[D_SZ];
    __shared__ float red[256];
    for (int d = t; d < D_SZ; d += 256) proto_s[d] = prototypes[(size_t)p * D_SZ + d];
    __syncthreads();

    float a = alpha[0], b = beta[0], th = theta[0];
    float pws_local = 0.f;
    for (int f = t; f < F_SZ; f += 256) {
        const float* fr = features + (size_t)f * D_SZ;
        float acc = 0.f;
#pragma unroll 8
        for (int d = 0; d < D_SZ; d++) acc += proto_s[d] * fr[d];
        float pp = fmaxf(acc, 0.f);
        float pw = acc * pp;
        g_W1[(size_t)p * F_SZ + f] = __float2bfloat16(th * pw + a * pp);
        g_W2[(size_t)p * F_SZ + f] = __float2bfloat16(b * pw);
        pws_local += pw;
    }
    red[t] = pws_local;
    __syncthreads();
    for (int s = 128; s > 0; s >>= 1) {
        if (t < s) red[t] += red[t + s];
        __syncthreads();
    }
    if (t == 0) g_biasP[p] = -b * red[0];
}

// =========================== kernel 2: stage 1 (TF32 wmma) ===========================
// Per CTA: 64 rows of x, all F=512 cols. 8 warps, warp tile 64x64 (warp w covers f=w*64..+63).
// Output: g_R (bf16 relu) and g_rowbias = -alpha * sum_f relu^2.
__global__ __launch_bounds__(256, 1)
void stage1_kernel(const float* __restrict__ x,
                   const float* __restrict__ features,
                   const float* __restrict__ alpha) {
    extern __shared__ float sm1[];           // 128 KB: As (64x256, 64KB) then reused as Outs (64x512, 128KB)
    float* As   = sm1;
    float* Outs = sm1;

    int tid  = threadIdx.x;
    int warp = tid >> 5;
    int lane = tid & 31;
    int m0   = blockIdx.x * 64;

    // stage x tile into smem (fp32)
    {
        const float4* xt = (const float4*)(x + (size_t)m0 * D_SZ);
        float4* As4 = (float4*)As;
        for (int i = tid; i < 64 * D_SZ / 4; i += 256) As4[i] = xt[i];
    }
    __syncthreads();

    using FragA = wmma::fragment<wmma::matrix_a, 16, 16, 8, wmma::precision::tf32, wmma::row_major>;
    using FragB = wmma::fragment<wmma::matrix_b, 16, 16, 8, wmma::precision::tf32, wmma::col_major>;
    using FragC = wmma::fragment<wmma::accumulator, 16, 16, 8, float>;

    FragC c[4][4];
#pragma unroll
    for (int i = 0; i < 4; i++)
#pragma unroll
        for (int j = 0; j < 4; j++) wmma::fill_fragment(c[i][j], 0.f);

    int f0 = warp * 64;
#pragma unroll 4
    for (int k0 = 0; k0 < D_SZ; k0 += 8) {
        FragA a[4];
#pragma unroll
        for (int i = 0; i < 4; i++) {
            wmma::load_matrix_sync(a[i], As + (i * 16) * D_SZ + k0, D_SZ);
#pragma unroll
            for (int e = 0; e < a[i].num_elements; e++)
                a[i].x[e] = wmma::__float_to_tf32(a[i].x[e]);
        }
#pragma unroll
        for (int j = 0; j < 4; j++) {
            FragB b;
            // B[k=d][n=f] = features[f][d]: col_major, ld = D
            wmma::load_matrix_sync(b, features + (size_t)(f0 + j * 16) * D_SZ + k0, D_SZ);
#pragma unroll
            for (int e = 0; e < b.num_elements; e++)
                b.x[e] = wmma::__float_to_tf32(b.x[e]);
#pragma unroll
            for (int i = 0; i < 4; i++) wmma::mma_sync(c[i][j], a[i], b, c[i][j]);
        }
    }
    __syncthreads();  // done with As

#pragma unroll
    for (int i = 0; i < 4; i++)
#pragma unroll
        for (int j = 0; j < 4; j++)
            wmma::store_matrix_sync(Outs + (i * 16) * F_SZ + f0 + j * 16, c[i][j],
                                    F_SZ, wmma::mem_row_major);
    __syncthreads();

    // relu -> store R (bf16, coalesced) ; keep relu'd values in smem for row sums
    __nv_bfloat16* Rg = g_R + (size_t)m0 * F_SZ;
    for (int i = tid; i < 64 * F_SZ; i += 256) {
        float r = fmaxf(Outs[i], 0.f);
        Outs[i] = r;
        Rg[i] = __float2bfloat16(r);
    }
    __syncthreads();

    // row sums of r^2: one warp handles 8 rows
    float av = alpha[0];
    for (int r = warp * 8; r < warp * 8 + 8; r++) {
        float s = 0.f;
        for (int cix = lane; cix < F_SZ; cix += 32) {
            float v = Outs[r * F_SZ + cix];
            s += v * v;
        }
#pragma unroll
        for (int o = 16; o > 0; o >>= 1) s += __shfl_xor_sync(0xffffffffu, s, o);
        if (lane == 0) g_rowbias[m0 + r] = -av * s;
    }
}

// =========================== kernel 3: stage 2 (bf16 wmma) ===========================
// Per CTA: 128 rows, all P=256 cols. K = 2F = 1024 logically: phase A=R^2 with W1, A=R with W2.
// R^2 is produced by elementwise-squaring the A fragment in registers.
__global__ __launch_bounds__(256, 1)
void stage2_kernel(float* __restrict__ out) {
    extern __shared__ char sm2raw[];
    __nv_bfloat16* Rs  = (__nv_bfloat16*)sm2raw;      // 128 x 512 bf16 = 128 KB
    __nv_bfloat16* Ws1 = Rs + 128 * F_SZ;             // 256 x 64 bf16  = 32 KB
    __nv_bfloat16* Ws2 = Ws1 + P_SZ * 64;             // 256 x 64 bf16  = 32 KB

    int tid  = threadIdx.x;
    int warp = tid >> 5;
    int wm   = warp >> 2;  // 0..1 -> 64-row slab
    int wn   = warp & 3;   // 0..3 -> 64-col slab
    int m0   = blockIdx.x * 128;

    // stage R tile
    {
        const float4* Rg4 = (const float4*)(g_R + (size_t)m0 * F_SZ);
        float4* Rs4 = (float4*)Rs;
        for (int i = tid; i < 128 * F_SZ / 8; i += 256) Rs4[i] = Rg4[i];
    }

    using FA = wmma::fragment<wmma::matrix_a, 16, 16, 16, __nv_bfloat16, wmma::row_major>;
    using FB = wmma::fragment<wmma::matrix_b, 16, 16, 16, __nv_bfloat16, wmma::col_major>;
    using FC = wmma::fragment<wmma::accumulator, 16, 16, 16, float>;

    FC c[4][4];
#pragma unroll
    for (int i = 0; i < 4; i++)
#pragma unroll
        for (int j = 0; j < 4; j++) wmma::fill_fragment(c[i][j], 0.f);

    int mrow = wm * 64, ncol = wn * 64;

    for (int kc = 0; kc < F_SZ; kc += 64) {
        __syncthreads();  // covers R staging on first iter, W reuse on later iters
        // stage W1/W2 chunk [256 x 64] (row n major, ld=64)
        {
            float4* w1 = (float4*)Ws1;
            float4* w2 = (float4*)Ws2;
            for (int i = tid; i < P_SZ * 8; i += 256) {
                int n = i >> 3, q = i & 7;
                w1[i] = ((const float4*)(g_W1 + (size_t)n * F_SZ + kc))[q];
                w2[i] = ((const float4*)(g_W2 + (size_t)n * F_SZ + kc))[q];
            }
        }
        __syncthreads();

#pragma unroll
        for (int k0 = 0; k0 < 64; k0 += 16) {
            FA a[4], a2[4];
#pragma unroll
            for (int i = 0; i < 4; i++) {
                wmma::load_matrix_sync(a[i], Rs + (mrow + i * 16) * F_SZ + kc + k0, F_SZ);
#pragma unroll
                for (int e = 0; e < a[i].num_elements; e++)
                    a2[i].x[e] = a[i].x[e] * a[i].x[e];
            }
#pragma unroll
            for (int j = 0; j < 4; j++) {
                FB b1, b2;
                wmma::load_matrix_sync(b1, Ws1 + (ncol + j * 16) * 64 + k0, 64);
                wmma::load_matrix_sync(b2, Ws2 + (ncol + j * 16) * 64 + k0, 64);
#pragma unroll
                for (int i = 0; i < 4; i++) {
                    wmma::mma_sync(c[i][j], a2[i], b1, c[i][j]);
                    wmma::mma_sync(c[i][j], a[i], b2, c[i][j]);
                }
            }
        }
    }
    __syncthreads();

    // epilogue: accum -> smem fp32 -> add biases -> coalesced out
    float* Os = (float*)sm2raw;  // 128 x 256 fp32 = 128 KB (overlaps Rs, which is dead)
#pragma unroll
    for (int i = 0; i < 4; i++)
#pragma unroll
        for (int j = 0; j < 4; j++)
            wmma::store_matrix_sync(Os + (mrow + i * 16) * P_SZ + ncol + j * 16, c[i][j],
                                    P_SZ, wmma::mem_row_major);
    __syncthreads();

    for (int i = tid; i < 128 * P_SZ; i += 256) {
        int r = i >> 8;
        int p = i & 255;
        out[(size_t)(m0 + r) * P_SZ + p] = Os[i] + g_rowbias[m0 + r] + g_biasP[p];
    }
}

// =========================== launch ===========================
extern "C" void kernel_launch(void* const* d_in, const int* in_sizes, int n_in,
                              void* d_out, int out_size) {
    const float* x          = (const float*)d_in[0];
    const float* features   = (const float*)d_in[1];
    const float* prototypes = (const float*)d_in[2];
    const float* alpha      = (const float*)d_in[3];
    const float* beta       = (const float*)d_in[4];
    const float* theta      = (const float*)d_in[5];
    float* out = (float*)d_out;

    cudaFuncSetAttribute(stage1_kernel, cudaFuncAttributeMaxDynamicSharedMemorySize, 128 * 1024);
    cudaFuncSetAttribute(stage2_kernel, cudaFuncAttributeMaxDynamicSharedMemorySize, 192 * 1024);

    pside_kernel<<<P_SZ, 256>>>(prototypes, features, alpha, beta, theta);
    stage1_kernel<<<B_SZ / 64, 256, 128 * 1024>>>(x, features, alpha);
    stage2_kernel<<<B_SZ / 128, 256, 192 * 1024>>>(out);
}

// round 2
// speedup vs baseline: 1.0912x; 1.0912x over previous
#include <cuda_runtime.h>
#include <cuda_bf16.h>
#include <mma.h>

using namespace nvcuda;

#define B_SZ 65536
#define D_SZ 256
#define F_SZ 512
#define P_SZ 256

// ---------------- scratch (static device globals; no allocations) ----------------
__device__ __nv_bfloat16 g_W1[P_SZ * F_SZ];   // theta*pw + alpha*pp
__device__ __nv_bfloat16 g_W2[P_SZ * F_SZ];   // beta*pw
__device__ float         g_biasP[P_SZ];       // -beta * pws[p]

// ===================== kernel 1: p-side precompute (tf32 wmma) =====================
// grid = P/64 = 4 CTAs; per CTA: 64 prototype rows x all F=512 cols.
// 8 warps, each owns a 64x64 warp tile (warp w -> f-slab w*64).
__global__ __launch_bounds__(256, 1)
void pside_kernel(const float* __restrict__ prototypes,
                  const float* __restrict__ features,
                  const float* __restrict__ alpha,
                  const float* __restrict__ beta,
                  const float* __restrict__ theta) {
    extern __shared__ float smp[];   // 128 KB: ps (64x256 fp32, 64KB) then reused as Outs (64x512 fp32, 128KB)
    float* ps   = smp;
    float* Outs = smp;

    int tid  = threadIdx.x;
    int warp = tid >> 5;
    int lane = tid & 31;
    int p0   = blockIdx.x * 64;

    {
        const float4* src = (const float4*)(prototypes + (size_t)p0 * D_SZ);
        float4* dst = (float4*)ps;
        for (int i = tid; i < 64 * D_SZ / 4; i += 256) dst[i] = src[i];
    }
    __syncthreads();

    using FragA = wmma::fragment<wmma::matrix_a, 16, 16, 8, wmma::precision::tf32, wmma::row_major>;
    using FragB = wmma::fragment<wmma::matrix_b, 16, 16, 8, wmma::precision::tf32, wmma::col_major>;
    using FragC = wmma::fragment<wmma::accumulator, 16, 16, 8, float>;

    FragC c[4][4];
#pragma unroll
    for (int i = 0; i < 4; i++)
#pragma unroll
        for (int j = 0; j < 4; j++) wmma::fill_fragment(c[i][j], 0.f);

    int f0 = warp * 64;
#pragma unroll 4
    for (int k0 = 0; k0 < D_SZ; k0 += 8) {
        FragA a[4];
#pragma unroll
        for (int i = 0; i < 4; i++) {
            wmma::load_matrix_sync(a[i], ps + (i * 16) * D_SZ + k0, D_SZ);
#pragma unroll
            for (int e = 0; e < a[i].num_elements; e++)
                a[i].x[e] = wmma::__float_to_tf32(a[i].x[e]);
        }
#pragma unroll
        for (int j = 0; j < 4; j++) {
            FragB b;
            wmma::load_matrix_sync(b, features + (size_t)(f0 + j * 16) * D_SZ + k0, D_SZ);
#pragma unroll
            for (int e = 0; e < b.num_elements; e++)
                b.x[e] = wmma::__float_to_tf32(b.x[e]);
#pragma unroll
            for (int i = 0; i < 4; i++) wmma::mma_sync(c[i][j], a[i], b, c[i][j]);
        }
    }
    __syncthreads();   // ps dead; Outs takes over the buffer

#pragma unroll
    for (int i = 0; i < 4; i++)
#pragma unroll
        for (int j = 0; j < 4; j++)
            wmma::store_matrix_sync(Outs + (i * 16) * F_SZ + f0 + j * 16, c[i][j],
                                    F_SZ, wmma::mem_row_major);
    __syncthreads();

    float a_ = alpha[0], b_ = beta[0], th = theta[0];
    // W1/W2 writes
    for (int i = tid; i < 64 * F_SZ; i += 256) {
        int pr = i >> 9, f = i & 511;
        float acc = Outs[i];
        float pp = fmaxf(acc, 0.f);
        float pw = acc * pp;
        g_W1[(size_t)(p0 + pr) * F_SZ + f] = __float2bfloat16(th * pw + a_ * pp);
        g_W2[(size_t)(p0 + pr) * F_SZ + f] = __float2bfloat16(b_ * pw);
    }
    // pws row sums: warp w -> rows w*8..w*8+7
    for (int r = warp * 8; r < warp * 8 + 8; r++) {
        float s = 0.f;
        for (int cix = lane; cix < F_SZ; cix += 32) {
            float acc = Outs[r * F_SZ + cix];
            s += acc * fmaxf(acc, 0.f);
        }
#pragma unroll
        for (int o = 16; o > 0; o >>= 1) s += __shfl_xor_sync(0xffffffffu, s, o);
        if (lane == 0) g_biasP[p0 + r] = -b_ * s;
    }
}

// ===================== kernel 2: fused stage1+stage2 =====================
// Per CTA: 128 rows of x. Phase A: R = relu(x @ F^T) (tf32 wmma, two 64-row halves),
// kept resident in smem as bf16. Phase B: out = [R^2 | R] @ [W1 | W2]^T (bf16 wmma)
// + row bias (-alpha*sum r^2) + col bias (-beta*pws).
//
// smem layout (dynamic):
//   [0, 128K)        Rs   bf16[128][512]   (phase B reuses as Os fp32[128][256])
//   [128K, 192K)     buf: phase A = xs fp32[64][256]; phase B = Ws1/Ws2 bf16[256][64] each
//   [192K, +512)     rb   fp32[128]   row bias
//   [.. , +1K)       bp   fp32[256]   col bias copy
//   [.. , +8K)       stw  fp32[8][256] per-warp accumulation staging
#define RS_OFF   0
#define BUF_OFF  (128 * 1024)
#define RB_OFF   (192 * 1024)
#define BP_OFF   (RB_OFF + 512)
#define STW_OFF  (BP_OFF + 1024)
#define SMEM_FUSED (STW_OFF + 8 * 256 * 4)

__global__ __launch_bounds__(256, 1)
void fused_kernel(const float* __restrict__ x,
                  const float* __restrict__ features,
                  const float* __restrict__ alpha,
                  float* __restrict__ out) {
    extern __shared__ char smraw[];
    __nv_bfloat16* Rs = (__nv_bfloat16*)(smraw + RS_OFF);
    float*         rb = (float*)(smraw + RB_OFF);
    float*         bp = (float*)(smraw + BP_OFF);

    int tid  = threadIdx.x;
    int warp = tid >> 5;
    int lane = tid & 31;
    int m0   = blockIdx.x * 128;

    // ---------------- Phase A: stage 1 (tf32), two 64-row halves ----------------
    using FA1 = wmma::fragment<wmma::matrix_a, 16, 16, 8, wmma::precision::tf32, wmma::row_major>;
    using FB1 = wmma::fragment<wmma::matrix_b, 16, 16, 8, wmma::precision::tf32, wmma::col_major>;
    using FC1 = wmma::fragment<wmma::accumulator, 16, 16, 8, float>;

    for (int h = 0; h < 2; h++) {
        float* xs = (float*)(smraw + BUF_OFF);
        {
            const float4* src = (const float4*)(x + (size_t)(m0 + h * 64) * D_SZ);
            float4* dst = (float4*)xs;
            for (int i = tid; i < 64 * D_SZ / 4; i += 256) dst[i] = src[i];
        }
        __syncthreads();

        FC1 c[4][4];
#pragma unroll
        for (int i = 0; i < 4; i++)
#pragma unroll
            for (int j = 0; j < 4; j++) wmma::fill_fragment(c[i][j], 0.f);

        int f0 = warp * 64;
#pragma unroll 4
        for (int k0 = 0; k0 < D_SZ; k0 += 8) {
            FA1 a[4];
#pragma unroll
            for (int i = 0; i < 4; i++) {
                wmma::load_matrix_sync(a[i], xs + (i * 16) * D_SZ + k0, D_SZ);
#pragma unroll
                for (int e = 0; e < a[i].num_elements; e++)
                    a[i].x[e] = wmma::__float_to_tf32(a[i].x[e]);
            }
#pragma unroll
            for (int j = 0; j < 4; j++) {
                FB1 b;
                wmma::load_matrix_sync(b, features + (size_t)(f0 + j * 16) * D_SZ + k0, D_SZ);
#pragma unroll
                for (int e = 0; e < b.num_elements; e++)
                    b.x[e] = wmma::__float_to_tf32(b.x[e]);
#pragma unroll
                for (int i = 0; i < 4; i++) wmma::mma_sync(c[i][j], a[i], b, c[i][j]);
            }
        }

        // per-warp epilogue: accum -> stw staging -> relu -> bf16 into Rs
        float* stw = (float*)(smraw + STW_OFF) + warp * 256;
#pragma unroll
        for (int i = 0; i < 4; i++) {
#pragma unroll
            for (int j = 0; j < 4; j++) {
                wmma::store_matrix_sync(stw, c[i][j], 16, wmma::mem_row_major);
                __syncwarp();
#pragma unroll
                for (int e = 0; e < 8; e++) {
                    int idx = lane * 8 + e;
                    int rr = idx >> 4, cc = idx & 15;
                    float v = fmaxf(stw[idx], 0.f);
                    Rs[(h * 64 + i * 16 + rr) * F_SZ + f0 + j * 16 + cc] = __float2bfloat16(v);
                }
                __syncwarp();
            }
        }
        __syncthreads();   // xs reload / Rs complete for this half
    }

    // row bias: rb[r] = -alpha * sum_f r^2   (from bf16 Rs, squared in fp32)
    {
        float av = alpha[0];
        for (int r = warp * 16; r < warp * 16 + 16; r++) {
            float s = 0.f;
            for (int cix = lane; cix < F_SZ; cix += 32) {
                float v = __bfloat162float(Rs[r * F_SZ + cix]);
                s += v * v;
            }
#pragma unroll
            for (int o = 16; o > 0; o >>= 1) s += __shfl_xor_sync(0xffffffffu, s, o);
            if (lane == 0) rb[r] = -av * s;
        }
    }

    // ---------------- Phase B: stage 2 (bf16), K = 512 x {R^2 w/ W1, R w/ W2} ----------------
    using FA2 = wmma::fragment<wmma::matrix_a, 16, 16, 16, __nv_bfloat16, wmma::row_major>;
    using FB2 = wmma::fragment<wmma::matrix_b, 16, 16, 16, __nv_bfloat16, wmma::col_major>;
    using FC2 = wmma::fragment<wmma::accumulator, 16, 16, 16, float>;

    __nv_bfloat16* Ws1 = (__nv_bfloat16*)(smraw + BUF_OFF);
    __nv_bfloat16* Ws2 = Ws1 + P_SZ * 64;

    int wm = warp >> 2;      // 0..1 -> 64-row slab
    int wn = warp & 3;       // 0..3 -> 64-col slab
    int mrow = wm * 64, ncol = wn * 64;

    FC2 c2[4][4];
#pragma unroll
    for (int i = 0; i < 4; i++)
#pragma unroll
        for (int j = 0; j < 4; j++) wmma::fill_fragment(c2[i][j], 0.f);

    for (int kc = 0; kc < F_SZ; kc += 64) {
        __syncthreads();
        {
            float4* w1 = (float4*)Ws1;
            float4* w2 = (float4*)Ws2;
            for (int i = tid; i < P_SZ * 8; i += 256) {
                int n = i >> 3, q = i & 7;
                w1[i] = ((const float4*)(g_W1 + (size_t)n * F_SZ + kc))[q];
                w2[i] = ((const float4*)(g_W2 + (size_t)n * F_SZ + kc))[q];
            }
        }
        __syncthreads();

#pragma unroll
        for (int k0 = 0; k0 < 64; k0 += 16) {
            FA2 a[4], a2[4];
#pragma unroll
            for (int i = 0; i < 4; i++) {
                wmma::load_matrix_sync(a[i], Rs + (mrow + i * 16) * F_SZ + kc + k0, F_SZ);
#pragma unroll
                for (int e = 0; e < a[i].num_elements; e++)
                    a2[i].x[e] = a[i].x[e] * a[i].x[e];
            }
#pragma unroll
            for (int j = 0; j < 4; j++) {
                FB2 b1, b2;
                wmma::load_matrix_sync(b1, Ws1 + (ncol + j * 16) * 64 + k0, 64);
                wmma::load_matrix_sync(b2, Ws2 + (ncol + j * 16) * 64 + k0, 64);
#pragma unroll
                for (int i = 0; i < 4; i++) {
                    wmma::mma_sync(c2[i][j], a2[i], b1, c2[i][j]);
                    wmma::mma_sync(c2[i][j], a[i], b2, c2[i][j]);
                }
            }
        }
    }
    __syncthreads();   // Rs dead -> Os takes over

    // epilogue
    float* Os = (float*)(smraw + RS_OFF);   // 128 x 256 fp32 = 128 KB
    for (int i = tid; i < P_SZ; i += 256) bp[i] = g_biasP[i];
#pragma unroll
    for (int i = 0; i < 4; i++)
#pragma unroll
        for (int j = 0; j < 4; j++)
            wmma::store_matrix_sync(Os + (mrow + i * 16) * P_SZ + ncol + j * 16, c2[i][j],
                                    P_SZ, wmma::mem_row_major);
    __syncthreads();

    for (int i = tid; i < 128 * P_SZ; i += 256) {
        int r = i >> 8;
        int p = i & 255;
        out[(size_t)(m0 + r) * P_SZ + p] = Os[i] + rb[r] + bp[p];
    }
}

// =========================== launch ===========================
extern "C" void kernel_launch(void* const* d_in, const int* in_sizes, int n_in,
                              void* d_out, int out_size) {
    const float* x          = (const float*)d_in[0];
    const float* features   = (const float*)d_in[1];
    const float* prototypes = (const float*)d_in[2];
    const float* alpha      = (const float*)d_in[3];
    const float* beta       = (const float*)d_in[4];
    const float* theta      = (const float*)d_in[5];
    float* out = (float*)d_out;

    cudaFuncSetAttribute(pside_kernel, cudaFuncAttributeMaxDynamicSharedMemorySize, 128 * 1024);
    cudaFuncSetAttribute(fused_kernel, cudaFuncAttributeMaxDynamicSharedMemorySize, SMEM_FUSED);

    pside_kernel<<<P_SZ / 64, 256, 128 * 1024>>>(prototypes, features, alpha, beta, theta);
    fused_kernel<<<B_SZ / 128, 256, SMEM_FUSED>>>(x, features, alpha, out);
}